// round 4
// baseline (speedup 1.0000x reference)
#include <cuda_runtime.h>
#include <math.h>

// ---------------- problem constants ----------------
#define NB 16              // buckets = 2 classes * 8 subgroups
#define NP 512             // points per bucket
#define ND 512             // feature dim
#define N2 (512*512)
#define NPAIR 56           // 2 classes * 28 subgroup pairs
#define NTASK (NPAIR*4)    // 4 softmin tasks per pair per step

// scratch layout (in floats)
constexpr size_t OFF_FEATS   = 0;
constexpr size_t OFF_SQN     = OFF_FEATS + (size_t)NB*N2;          // 8192 squared norms
constexpr size_t OFF_DMIN    = OFF_SQN + 8192;
constexpr size_t OFF_DMAX    = OFF_DMIN + 8192;
constexpr size_t OFF_EPS0    = OFF_DMAX + 8192;                    // 56 eps0 (pad 64)
constexpr size_t OFF_CCROSS  = OFF_EPS0 + 64;                      // 56 cross cost matrices
constexpr size_t OFF_CCROSST = OFF_CCROSS + (size_t)NPAIR*N2;      // transposes
constexpr size_t OFF_CSELF   = OFF_CCROSST + (size_t)NPAIR*N2;     // 16 self cost matrices
constexpr size_t OFF_POT     = OFF_CSELF + (size_t)NB*N2;          // 2 x 224 x 512 potentials
constexpr size_t SCRATCH_TOTAL = OFF_POT + (size_t)2*NTASK*512;

__device__ __align__(16) float g_scratch[SCRATCH_TOTAL];
__device__ int   g_idx[NB*NP];   // bucket*512+rank -> original sample index

// triu_indices(8, k=1)
__constant__ int c_pa[28] = {0,0,0,0,0,0,0,1,1,1,1,1,1,2,2,2,2,2,3,3,3,3,4,4,4,5,5,6};
__constant__ int c_pb[28] = {1,2,3,4,5,6,7,2,3,4,5,6,7,3,4,5,6,7,4,5,6,7,5,6,7,6,7,7};

__device__ __forceinline__ float ex2f(float x) {
    float y;
    asm("ex2.approx.ftz.f32 %0, %1;" : "=f"(y) : "f"(x));
    return y;
}

// ---------------- stage 1: stable counting sort (rank within bucket) ----------------
// one block per key (16 keys), stable by ascending original index.
__global__ void rank_kernel(const int* __restrict__ labels, const int* __restrict__ subgroups) {
    __shared__ int s[256];
    __shared__ int sbase;
    int key = blockIdx.x;
    if (threadIdx.x == 0) sbase = 0;
    __syncthreads();
    for (int c0 = 0; c0 < 8192; c0 += 256) {
        int i = c0 + threadIdx.x;
        int k = labels[i] * 8 + subgroups[i];
        int f = (k == key) ? 1 : 0;
        s[threadIdx.x] = f;
        __syncthreads();
        #pragma unroll
        for (int off = 1; off < 256; off <<= 1) {
            int v = (threadIdx.x >= (unsigned)off) ? s[threadIdx.x - off] : 0;
            __syncthreads();
            s[threadIdx.x] += v;
            __syncthreads();
        }
        if (f) g_idx[key * NP + sbase + s[threadIdx.x] - 1] = i;
        __syncthreads();
        if (threadIdx.x == 0) sbase += s[255];
        __syncthreads();
    }
}

// ---------------- stage 2: gather + norms + per-dim min/max + eps0 ----------------
__global__ void gather_kernel(const float* __restrict__ feats) {
    size_t total = (size_t)NB * N2;
    for (size_t idx = (size_t)blockIdx.x * blockDim.x + threadIdx.x; idx < total;
         idx += (size_t)gridDim.x * blockDim.x) {
        int d   = (int)(idx & 511);
        int r   = (int)((idx >> 9) & 511);
        int bkt = (int)(idx >> 18);
        g_scratch[OFF_FEATS + idx] = feats[(size_t)g_idx[bkt * NP + r] * ND + d];
    }
}

__global__ void sqn_kernel() {  // warp per gathered row
    int wid = threadIdx.x >> 5, lane = threadIdx.x & 31;
    int row = blockIdx.x * 8 + wid;               // 0..8191
    const float* f = g_scratch + OFF_FEATS + (size_t)row * ND;
    float s = 0.f;
    #pragma unroll
    for (int q = 0; q < 16; q++) { float v = f[lane + q * 32]; s = fmaf(v, v, s); }
    #pragma unroll
    for (int off = 16; off; off >>= 1) s += __shfl_xor_sync(0xffffffffu, s, off);
    if (lane == 0) g_scratch[OFF_SQN + row] = s;
}

__global__ void minmax_kernel() {  // thread per (bucket, dim)
    int idx = blockIdx.x * 256 + threadIdx.x;      // 0..8191
    int b = idx >> 9, d = idx & 511;
    const float* base = g_scratch + OFF_FEATS + (size_t)b * N2 + d;
    float mn = base[0], mx = base[0];
    for (int p = 1; p < NP; p++) {
        float v = base[(size_t)p * ND];
        mn = fminf(mn, v); mx = fmaxf(mx, v);
    }
    g_scratch[OFF_DMIN + idx] = mn;
    g_scratch[OFF_DMAX + idx] = mx;
}

__global__ void eps0_kernel() {  // warp per pair
    int w = blockIdx.x * 8 + (threadIdx.x >> 5);
    int lane = threadIdx.x & 31;
    if (w >= NPAIR) return;
    int kk = w % 28, cls = w / 28;
    int a = cls * 8 + c_pa[kk], b = cls * 8 + c_pb[kk];
    const float* dmin = g_scratch + OFF_DMIN;
    const float* dmax = g_scratch + OFF_DMAX;
    float s = 0.f;
    #pragma unroll
    for (int q = 0; q < 16; q++) {
        int d = lane + q * 32;
        float mx = fmaxf(dmax[a * ND + d], dmax[b * ND + d]);
        float mn = fminf(dmin[a * ND + d], dmin[b * ND + d]);
        float rr = mx - mn;
        s = fmaf(rr, rr, s);
    }
    #pragma unroll
    for (int off = 16; off; off >>= 1) s += __shfl_xor_sync(0xffffffffu, s, off);
    if (lane == 0) {
        float diam = sqrtf(s);
        g_scratch[OFF_EPS0 + w] = diam * diam;   // diameter ** 2
    }
}

// ---------------- stage 3: cost matrices  C = max(0.5(|x|^2+|y|^2) - x.y, 0) --------
// 72 jobs: 56 cross + 16 self. 64x64 tile / block, 256 thr, 4x4 microtile.
__global__ void gemm_kernel() {
    int job = blockIdx.y;
    int ta, tb; size_t outoff;
    if (job < NPAIR) {
        int cls = job / 28, k = job % 28;
        ta = cls * 8 + c_pa[k]; tb = cls * 8 + c_pb[k];
        outoff = OFF_CCROSS + (size_t)job * N2;
    } else {
        int sb = job - NPAIR;
        ta = tb = sb;
        outoff = OFF_CSELF + (size_t)sb * N2;
    }
    int tm = (blockIdx.x >> 3) << 6;
    int tn = (blockIdx.x & 7) << 6;
    const float* A = g_scratch + OFF_FEATS + (size_t)ta * N2;
    const float* B = g_scratch + OFF_FEATS + (size_t)tb * N2;

    __shared__ float As[32][68];   // [k][m]
    __shared__ float Bs[32][68];   // [k][n]

    int tid = threadIdx.x;
    int tx = tid & 15, ty = tid >> 4;
    int r  = tid >> 3;             // 0..31
    int c4 = (tid & 7) << 2;       // 0..28

    float acc[4][4];
    #pragma unroll
    for (int i = 0; i < 4; i++)
        #pragma unroll
        for (int j = 0; j < 4; j++) acc[i][j] = 0.f;

    for (int k0 = 0; k0 < ND; k0 += 32) {
        float4 a0 = *(const float4*)(A + (size_t)(tm + r)      * ND + k0 + c4);
        float4 a1 = *(const float4*)(A + (size_t)(tm + r + 32) * ND + k0 + c4);
        float4 b0 = *(const float4*)(B + (size_t)(tn + r)      * ND + k0 + c4);
        float4 b1 = *(const float4*)(B + (size_t)(tn + r + 32) * ND + k0 + c4);
        As[c4+0][r] = a0.x; As[c4+1][r] = a0.y; As[c4+2][r] = a0.z; As[c4+3][r] = a0.w;
        As[c4+0][r+32] = a1.x; As[c4+1][r+32] = a1.y; As[c4+2][r+32] = a1.z; As[c4+3][r+32] = a1.w;
        Bs[c4+0][r] = b0.x; Bs[c4+1][r] = b0.y; Bs[c4+2][r] = b0.z; Bs[c4+3][r] = b0.w;
        Bs[c4+0][r+32] = b1.x; Bs[c4+1][r+32] = b1.y; Bs[c4+2][r+32] = b1.z; Bs[c4+3][r+32] = b1.w;
        __syncthreads();
        #pragma unroll
        for (int kk = 0; kk < 32; kk++) {
            float4 av = *(const float4*)&As[kk][ty << 2];
            float4 bv = *(const float4*)&Bs[kk][tx << 2];
            float a[4] = {av.x, av.y, av.z, av.w};
            float b[4] = {bv.x, bv.y, bv.z, bv.w};
            #pragma unroll
            for (int i = 0; i < 4; i++)
                #pragma unroll
                for (int j = 0; j < 4; j++) acc[i][j] = fmaf(a[i], b[j], acc[i][j]);
        }
        __syncthreads();
    }

    const float* sa = g_scratch + OFF_SQN + (size_t)ta * NP;
    const float* sb = g_scratch + OFF_SQN + (size_t)tb * NP;
    float* Co = g_scratch + outoff;
    #pragma unroll
    for (int i = 0; i < 4; i++) {
        int row = tm + (ty << 2) + i;
        float h = 0.5f * sa[row];
        #pragma unroll
        for (int j = 0; j < 4; j++) {
            int col = tn + (tx << 2) + j;
            Co[(size_t)row * NP + col] = fmaxf(h + 0.5f * sb[col] - acc[i][j], 0.0f);
        }
    }
}

// transpose the 56 cross matrices
__global__ void transpose_kernel() {
    __shared__ float tile[32][33];
    const float* in = g_scratch + OFF_CCROSS  + (size_t)blockIdx.z * N2;
    float* out      = g_scratch + OFF_CCROSST + (size_t)blockIdx.z * N2;
    int x = blockIdx.x * 32 + threadIdx.x;
    int y0 = blockIdx.y * 32;
    #pragma unroll
    for (int j = 0; j < 32; j += 8)
        tile[threadIdx.y + j][threadIdx.x] = in[(size_t)(y0 + threadIdx.y + j) * NP + x];
    __syncthreads();
    int x2 = blockIdx.y * 32 + threadIdx.x;
    int y1 = blockIdx.x * 32;
    #pragma unroll
    for (int j = 0; j < 32; j += 8)
        out[(size_t)(y1 + threadIdx.y + j) * NP + x2] = tile[threadIdx.x][threadIdx.y + j];
}

// ---------------- stage 4: softmin iterations ----------------
// mode 0: init (eps = eps0, g = 0, no averaging)
// mode 1: scan step t (eps = max(eps0*0.81^t, 1e-8), out = 0.5*(old + softmin))
// mode 2: final pass (eps = 1e-8, no averaging)
// grid: (64, 224), block 256. warp per row, 16 C-elements per lane.
__global__ void softmin_kernel(int t, int mode, int bOld, int bNew) {
    __shared__ float gsc[512];
    __shared__ float sh_eps, sh_nk2;
    int task = blockIdx.y;
    int type = task / 56;
    int p = task - type * 56;
    int cls = p / 28, kk = p - cls * 28;
    int ba = cls * 8 + c_pa[kk], bb = cls * 8 + c_pb[kk];

    const float* C; int gslot, oslot;
    if (type == 0)      { C = g_scratch + OFF_CCROSS  + (size_t)p  * N2; gslot = 1; oslot = 0; }
    else if (type == 1) { C = g_scratch + OFF_CCROSST + (size_t)p  * N2; gslot = 0; oslot = 1; }
    else if (type == 2) { C = g_scratch + OFF_CSELF   + (size_t)ba * N2; gslot = 2; oslot = 2; }
    else                { C = g_scratch + OFF_CSELF   + (size_t)bb * N2; gslot = 3; oslot = 3; }

    const float* potOld = g_scratch + OFF_POT + (size_t)bOld * NTASK * 512;
    float*       potNew = g_scratch + OFF_POT + (size_t)bNew * NTASK * 512;
    const float* pin  = potOld + (size_t)(p * 4 + gslot) * 512;
    const float* pavg = potOld + (size_t)(p * 4 + oslot) * 512;
    float*       pout = potNew + (size_t)(p * 4 + oslot) * 512;

    if (threadIdx.x == 0) {
        float e0 = g_scratch[OFF_EPS0 + p];
        float eps;
        if (mode == 0)      eps = e0;
        else if (mode == 2) eps = 1e-8f;
        else                eps = fmaxf(e0 * powf(0.81f, (float)t), 1e-8f);
        sh_eps = eps;
        sh_nk2 = -1.4426950408889634f / eps;   // -log2(e)/eps
    }
    __syncthreads();
    float eps = sh_eps, nk2 = sh_nk2;

    // scaled potential into shared: gsc[j] = g_j * k2  (log2 domain)
    for (int i = threadIdx.x; i < 512; i += 256)
        gsc[i] = (mode == 0) ? 0.f : pin[i] * (-nk2);
    __syncthreads();

    int lane = threadIdx.x & 31;
    int row = blockIdx.x * 8 + (threadIdx.x >> 5);
    const float4* Crow = (const float4*)(C + (size_t)row * 512);
    const float4* G = (const float4*)gsc;

    float v[16];
    float vmax = -3.4e38f;
    #pragma unroll
    for (int q = 0; q < 4; q++) {
        float4 c = Crow[lane + q * 32];
        float4 g = G[lane + q * 32];
        v[q*4+0] = fmaf(c.x, nk2, g.x);
        v[q*4+1] = fmaf(c.y, nk2, g.y);
        v[q*4+2] = fmaf(c.z, nk2, g.z);
        v[q*4+3] = fmaf(c.w, nk2, g.w);
        vmax = fmaxf(vmax, fmaxf(fmaxf(v[q*4+0], v[q*4+1]), fmaxf(v[q*4+2], v[q*4+3])));
    }
    #pragma unroll
    for (int off = 16; off; off >>= 1)
        vmax = fmaxf(vmax, __shfl_xor_sync(0xffffffffu, vmax, off));
    float s = 0.f;
    #pragma unroll
    for (int q = 0; q < 16; q++) s += ex2f(v[q] - vmax);   // args <= 0, exact-safe
    #pragma unroll
    for (int off = 16; off; off >>= 1)
        s += __shfl_xor_sync(0xffffffffu, s, off);

    if (lane == 0) {
        // -eps*ln2*(vmax + log2(sum) - log2(512))
        float res = -eps * 0.6931471805599453f * (vmax + __log2f(s) - 9.0f);
        pout[row] = (mode == 1) ? 0.5f * (pavg[row] + res) : res;
    }
}

// ---------------- stage 5: final reduction ----------------
// slots per pair: 0=f_ba(+), 1=g_ab(+), 2=f_aa(-), 3=g_bb(-)
__global__ void reduce_kernel(int bFin, float* __restrict__ out) {
    __shared__ float sh[1024];
    const float* pot = g_scratch + OFF_POT + (size_t)bFin * NTASK * 512;
    float s = 0.f;
    for (int i = threadIdx.x; i < NTASK * 512; i += 1024) {
        int slot = (i >> 9) & 3;
        float v = pot[i];
        s += (slot < 2) ? v : -v;
    }
    sh[threadIdx.x] = s;
    __syncthreads();
    for (int off = 512; off; off >>= 1) {
        if (threadIdx.x < off) sh[threadIdx.x] += sh[threadIdx.x + off];
        __syncthreads();
    }
    if (threadIdx.x == 0) out[0] = sh[0] / (512.0f * 56.0f);
}

// ---------------- launch ----------------
extern "C" void kernel_launch(void* const* d_in, const int* in_sizes, int n_in,
                              void* d_out, int out_size) {
    const float* features  = (const float*)d_in[0];
    const int*   labels    = (const int*)d_in[1];
    const int*   subgroups = (const int*)d_in[2];
    float* out = (float*)d_out;

    rank_kernel<<<16, 256>>>(labels, subgroups);
    gather_kernel<<<4096, 256>>>(features);
    sqn_kernel<<<1024, 256>>>();
    minmax_kernel<<<32, 256>>>();
    eps0_kernel<<<7, 256>>>();
    gemm_kernel<<<dim3(64, 72), 256>>>();
    transpose_kernel<<<dim3(16, 16, 56), dim3(32, 8)>>>();

    dim3 sgrid(64, NTASK);
    // init: writes buffer 0
    softmin_kernel<<<sgrid, 256>>>(0, 0, 1, 0);
    // 140 scan steps: step t reads t%2, writes 1-t%2
    for (int t = 0; t < 140; t++) {
        int bOld = t & 1;
        softmin_kernel<<<sgrid, 256>>>(t, 1, bOld, 1 - bOld);
    }
    // after t=139 (odd), result sits in buffer 0; final pass writes buffer 1
    softmin_kernel<<<sgrid, 256>>>(0, 2, 0, 1);
    reduce_kernel<<<1, 1024>>>(1, out);
}

// round 5
// speedup vs baseline: 1.0020x; 1.0020x over previous
#include <cuda_runtime.h>
#include <math.h>

// ---------------- problem constants ----------------
#define NB 16              // buckets = 2 classes * 8 subgroups
#define NP 512             // points per bucket
#define ND 512             // feature dim
#define N2 (512*512)
#define NPAIR 56           // 2 classes * 28 subgroup pairs
#define NTASK (NPAIR*4)    // 4 softmin tasks per pair per step

// scratch layout (in floats)
constexpr size_t OFF_FEATS   = 0;
constexpr size_t OFF_SQN     = OFF_FEATS + (size_t)NB*N2;          // 8192 squared norms
constexpr size_t OFF_DMIN    = OFF_SQN + 8192;
constexpr size_t OFF_DMAX    = OFF_DMIN + 8192;
constexpr size_t OFF_EPS0    = OFF_DMAX + 8192;                    // 56 eps0 (pad 64)
constexpr size_t OFF_CCROSS  = OFF_EPS0 + 64;                      // 56 cross cost matrices
constexpr size_t OFF_CCROSST = OFF_CCROSS + (size_t)NPAIR*N2;      // transposes
constexpr size_t OFF_CSELF   = OFF_CCROSST + (size_t)NPAIR*N2;     // 16 self cost matrices
constexpr size_t OFF_POT     = OFF_CSELF + (size_t)NB*N2;          // 2 x 224 x 512 potentials
constexpr size_t SCRATCH_TOTAL = OFF_POT + (size_t)2*NTASK*512;

__device__ __align__(16) float g_scratch[SCRATCH_TOTAL];
__device__ int   g_idx[NB*NP];   // bucket*512+rank -> original sample index

// triu_indices(8, k=1)
__constant__ int c_pa[28] = {0,0,0,0,0,0,0,1,1,1,1,1,1,2,2,2,2,2,3,3,3,3,4,4,4,5,5,6};
__constant__ int c_pb[28] = {1,2,3,4,5,6,7,2,3,4,5,6,7,3,4,5,6,7,4,5,6,7,5,6,7,6,7,7};

__device__ __forceinline__ float ex2f(float x) {
    float y;
    asm("ex2.approx.ftz.f32 %0, %1;" : "=f"(y) : "f"(x));
    return y;
}

// ---------------- stage 1: stable counting sort (rank within bucket) ----------------
// one block per key (16 keys), stable by ascending original index.
__global__ void rank_kernel(const int* __restrict__ labels, const int* __restrict__ subgroups) {
    __shared__ int s[256];
    __shared__ int sbase;
    int key = blockIdx.x;
    if (threadIdx.x == 0) sbase = 0;
    __syncthreads();
    for (int c0 = 0; c0 < 8192; c0 += 256) {
        int i = c0 + threadIdx.x;
        int k = labels[i] * 8 + subgroups[i];
        int f = (k == key) ? 1 : 0;
        s[threadIdx.x] = f;
        __syncthreads();
        #pragma unroll
        for (int off = 1; off < 256; off <<= 1) {
            int v = (threadIdx.x >= (unsigned)off) ? s[threadIdx.x - off] : 0;
            __syncthreads();
            s[threadIdx.x] += v;
            __syncthreads();
        }
        if (f) g_idx[key * NP + sbase + s[threadIdx.x] - 1] = i;
        __syncthreads();
        if (threadIdx.x == 0) sbase += s[255];
        __syncthreads();
    }
}

// ---------------- stage 2: gather + norms + per-dim min/max + eps0 ----------------
__global__ void gather_kernel(const float* __restrict__ feats) {
    size_t total = (size_t)NB * N2;
    for (size_t idx = (size_t)blockIdx.x * blockDim.x + threadIdx.x; idx < total;
         idx += (size_t)gridDim.x * blockDim.x) {
        int d   = (int)(idx & 511);
        int r   = (int)((idx >> 9) & 511);
        int bkt = (int)(idx >> 18);
        g_scratch[OFF_FEATS + idx] = feats[(size_t)g_idx[bkt * NP + r] * ND + d];
    }
}

__global__ void sqn_kernel() {  // warp per gathered row
    int wid = threadIdx.x >> 5, lane = threadIdx.x & 31;
    int row = blockIdx.x * 8 + wid;               // 0..8191
    const float* f = g_scratch + OFF_FEATS + (size_t)row * ND;
    float s = 0.f;
    #pragma unroll
    for (int q = 0; q < 16; q++) { float v = f[lane + q * 32]; s = fmaf(v, v, s); }
    #pragma unroll
    for (int off = 16; off; off >>= 1) s += __shfl_xor_sync(0xffffffffu, s, off);
    if (lane == 0) g_scratch[OFF_SQN + row] = s;
}

__global__ void minmax_kernel() {  // thread per (bucket, dim)
    int idx = blockIdx.x * 256 + threadIdx.x;      // 0..8191
    int b = idx >> 9, d = idx & 511;
    const float* base = g_scratch + OFF_FEATS + (size_t)b * N2 + d;
    float mn = base[0], mx = base[0];
    for (int p = 1; p < NP; p++) {
        float v = base[(size_t)p * ND];
        mn = fminf(mn, v); mx = fmaxf(mx, v);
    }
    g_scratch[OFF_DMIN + idx] = mn;
    g_scratch[OFF_DMAX + idx] = mx;
}

__global__ void eps0_kernel() {  // warp per pair
    int w = blockIdx.x * 8 + (threadIdx.x >> 5);
    int lane = threadIdx.x & 31;
    if (w >= NPAIR) return;
    int kk = w % 28, cls = w / 28;
    int a = cls * 8 + c_pa[kk], b = cls * 8 + c_pb[kk];
    const float* dmin = g_scratch + OFF_DMIN;
    const float* dmax = g_scratch + OFF_DMAX;
    float s = 0.f;
    #pragma unroll
    for (int q = 0; q < 16; q++) {
        int d = lane + q * 32;
        float mx = fmaxf(dmax[a * ND + d], dmax[b * ND + d]);
        float mn = fminf(dmin[a * ND + d], dmin[b * ND + d]);
        float rr = mx - mn;
        s = fmaf(rr, rr, s);
    }
    #pragma unroll
    for (int off = 16; off; off >>= 1) s += __shfl_xor_sync(0xffffffffu, s, off);
    if (lane == 0) {
        float diam = sqrtf(s);
        g_scratch[OFF_EPS0 + w] = diam * diam;   // diameter ** 2
    }
}

// ---------------- stage 3: cost matrices  C = max(0.5(|x|^2+|y|^2) - x.y, 0) --------
// 72 jobs: 56 cross + 16 self. 64x64 tile / block, 256 thr, 4x4 microtile.
__global__ void gemm_kernel() {
    int job = blockIdx.y;
    int ta, tb; size_t outoff;
    if (job < NPAIR) {
        int cls = job / 28, k = job % 28;
        ta = cls * 8 + c_pa[k]; tb = cls * 8 + c_pb[k];
        outoff = OFF_CCROSS + (size_t)job * N2;
    } else {
        int sb = job - NPAIR;
        ta = tb = sb;
        outoff = OFF_CSELF + (size_t)sb * N2;
    }
    int tm = (blockIdx.x >> 3) << 6;
    int tn = (blockIdx.x & 7) << 6;
    const float* A = g_scratch + OFF_FEATS + (size_t)ta * N2;
    const float* B = g_scratch + OFF_FEATS + (size_t)tb * N2;

    __shared__ float As[32][68];   // [k][m]
    __shared__ float Bs[32][68];   // [k][n]

    int tid = threadIdx.x;
    int tx = tid & 15, ty = tid >> 4;
    int r  = tid >> 3;             // 0..31
    int c4 = (tid & 7) << 2;       // 0..28

    float acc[4][4];
    #pragma unroll
    for (int i = 0; i < 4; i++)
        #pragma unroll
        for (int j = 0; j < 4; j++) acc[i][j] = 0.f;

    for (int k0 = 0; k0 < ND; k0 += 32) {
        float4 a0 = *(const float4*)(A + (size_t)(tm + r)      * ND + k0 + c4);
        float4 a1 = *(const float4*)(A + (size_t)(tm + r + 32) * ND + k0 + c4);
        float4 b0 = *(const float4*)(B + (size_t)(tn + r)      * ND + k0 + c4);
        float4 b1 = *(const float4*)(B + (size_t)(tn + r + 32) * ND + k0 + c4);
        As[c4+0][r] = a0.x; As[c4+1][r] = a0.y; As[c4+2][r] = a0.z; As[c4+3][r] = a0.w;
        As[c4+0][r+32] = a1.x; As[c4+1][r+32] = a1.y; As[c4+2][r+32] = a1.z; As[c4+3][r+32] = a1.w;
        Bs[c4+0][r] = b0.x; Bs[c4+1][r] = b0.y; Bs[c4+2][r] = b0.z; Bs[c4+3][r] = b0.w;
        Bs[c4+0][r+32] = b1.x; Bs[c4+1][r+32] = b1.y; Bs[c4+2][r+32] = b1.z; Bs[c4+3][r+32] = b1.w;
        __syncthreads();
        #pragma unroll
        for (int kk = 0; kk < 32; kk++) {
            float4 av = *(const float4*)&As[kk][ty << 2];
            float4 bv = *(const float4*)&Bs[kk][tx << 2];
            float a[4] = {av.x, av.y, av.z, av.w};
            float b[4] = {bv.x, bv.y, bv.z, bv.w};
            #pragma unroll
            for (int i = 0; i < 4; i++)
                #pragma unroll
                for (int j = 0; j < 4; j++) acc[i][j] = fmaf(a[i], b[j], acc[i][j]);
        }
        __syncthreads();
    }

    const float* sa = g_scratch + OFF_SQN + (size_t)ta * NP;
    const float* sb = g_scratch + OFF_SQN + (size_t)tb * NP;
    float* Co = g_scratch + outoff;
    #pragma unroll
    for (int i = 0; i < 4; i++) {
        int row = tm + (ty << 2) + i;
        float h = 0.5f * sa[row];
        #pragma unroll
        for (int j = 0; j < 4; j++) {
            int col = tn + (tx << 2) + j;
            Co[(size_t)row * NP + col] = fmaxf(h + 0.5f * sb[col] - acc[i][j], 0.0f);
        }
    }
}

// transpose the 56 cross matrices
__global__ void transpose_kernel() {
    __shared__ float tile[32][33];
    const float* in = g_scratch + OFF_CCROSS  + (size_t)blockIdx.z * N2;
    float* out      = g_scratch + OFF_CCROSST + (size_t)blockIdx.z * N2;
    int x = blockIdx.x * 32 + threadIdx.x;
    int y0 = blockIdx.y * 32;
    #pragma unroll
    for (int j = 0; j < 32; j += 8)
        tile[threadIdx.y + j][threadIdx.x] = in[(size_t)(y0 + threadIdx.y + j) * NP + x];
    __syncthreads();
    int x2 = blockIdx.y * 32 + threadIdx.x;
    int y1 = blockIdx.x * 32;
    #pragma unroll
    for (int j = 0; j < 32; j += 8)
        out[(size_t)(y1 + threadIdx.y + j) * NP + x2] = tile[threadIdx.x][threadIdx.y + j];
}

// ---------------- stage 4: softmin iterations ----------------
// mode 0: init (eps = eps0, g = 0, no averaging)
// mode 1: scan step t (eps = max(eps0*0.81^t, 1e-8), out = 0.5*(old + softmin))
// mode 2: final pass (eps = 1e-8, no averaging)
// grid: (64, 224), block 256. warp per row, 16 C-elements per lane.
__global__ void softmin_kernel(int t, int mode, int bOld, int bNew) {
    __shared__ float gsc[512];
    __shared__ float sh_eps, sh_nk2;
    int task = blockIdx.y;
    int type = task / 56;
    int p = task - type * 56;
    int cls = p / 28, kk = p - cls * 28;
    int ba = cls * 8 + c_pa[kk], bb = cls * 8 + c_pb[kk];

    const float* C; int gslot, oslot;
    if (type == 0)      { C = g_scratch + OFF_CCROSS  + (size_t)p  * N2; gslot = 1; oslot = 0; }
    else if (type == 1) { C = g_scratch + OFF_CCROSST + (size_t)p  * N2; gslot = 0; oslot = 1; }
    else if (type == 2) { C = g_scratch + OFF_CSELF   + (size_t)ba * N2; gslot = 2; oslot = 2; }
    else                { C = g_scratch + OFF_CSELF   + (size_t)bb * N2; gslot = 3; oslot = 3; }

    const float* potOld = g_scratch + OFF_POT + (size_t)bOld * NTASK * 512;
    float*       potNew = g_scratch + OFF_POT + (size_t)bNew * NTASK * 512;
    const float* pin  = potOld + (size_t)(p * 4 + gslot) * 512;
    const float* pavg = potOld + (size_t)(p * 4 + oslot) * 512;
    float*       pout = potNew + (size_t)(p * 4 + oslot) * 512;

    if (threadIdx.x == 0) {
        float e0 = g_scratch[OFF_EPS0 + p];
        float eps;
        if (mode == 0)      eps = e0;
        else if (mode == 2) eps = 1e-8f;
        else                eps = fmaxf(e0 * powf(0.81f, (float)t), 1e-8f);
        sh_eps = eps;
        sh_nk2 = -1.4426950408889634f / eps;   // -log2(e)/eps
    }
    __syncthreads();
    float eps = sh_eps, nk2 = sh_nk2;

    // scaled potential into shared: gsc[j] = g_j * k2  (log2 domain)
    for (int i = threadIdx.x; i < 512; i += 256)
        gsc[i] = (mode == 0) ? 0.f : pin[i] * (-nk2);
    __syncthreads();

    int lane = threadIdx.x & 31;
    int row = blockIdx.x * 8 + (threadIdx.x >> 5);
    const float4* Crow = (const float4*)(C + (size_t)row * 512);
    const float4* G = (const float4*)gsc;

    float v[16];
    float vmax = -3.4e38f;
    #pragma unroll
    for (int q = 0; q < 4; q++) {
        float4 c = Crow[lane + q * 32];
        float4 g = G[lane + q * 32];
        v[q*4+0] = fmaf(c.x, nk2, g.x);
        v[q*4+1] = fmaf(c.y, nk2, g.y);
        v[q*4+2] = fmaf(c.z, nk2, g.z);
        v[q*4+3] = fmaf(c.w, nk2, g.w);
        vmax = fmaxf(vmax, fmaxf(fmaxf(v[q*4+0], v[q*4+1]), fmaxf(v[q*4+2], v[q*4+3])));
    }
    #pragma unroll
    for (int off = 16; off; off >>= 1)
        vmax = fmaxf(vmax, __shfl_xor_sync(0xffffffffu, vmax, off));
    float s = 0.f;
    #pragma unroll
    for (int q = 0; q < 16; q++) s += ex2f(v[q] - vmax);   // args <= 0, exact-safe
    #pragma unroll
    for (int off = 16; off; off >>= 1)
        s += __shfl_xor_sync(0xffffffffu, s, off);

    if (lane == 0) {
        // -eps*ln2*(vmax + log2(sum) - log2(512))
        float res = -eps * 0.6931471805599453f * (vmax + __log2f(s) - 9.0f);
        pout[row] = (mode == 1) ? 0.5f * (pavg[row] + res) : res;
    }
}

// ---------------- stage 5: final reduction ----------------
// slots per pair: 0=f_ba(+), 1=g_ab(+), 2=f_aa(-), 3=g_bb(-)
__global__ void reduce_kernel(int bFin, float* __restrict__ out) {
    __shared__ float sh[1024];
    const float* pot = g_scratch + OFF_POT + (size_t)bFin * NTASK * 512;
    float s = 0.f;
    for (int i = threadIdx.x; i < NTASK * 512; i += 1024) {
        int slot = (i >> 9) & 3;
        float v = pot[i];
        s += (slot < 2) ? v : -v;
    }
    sh[threadIdx.x] = s;
    __syncthreads();
    for (int off = 512; off; off >>= 1) {
        if (threadIdx.x < off) sh[threadIdx.x] += sh[threadIdx.x + off];
        __syncthreads();
    }
    if (threadIdx.x == 0) out[0] = sh[0] / (512.0f * 56.0f);
}

// ---------------- launch ----------------
extern "C" void kernel_launch(void* const* d_in, const int* in_sizes, int n_in,
                              void* d_out, int out_size) {
    const float* features  = (const float*)d_in[0];
    const int*   labels    = (const int*)d_in[1];
    const int*   subgroups = (const int*)d_in[2];
    float* out = (float*)d_out;

    rank_kernel<<<16, 256>>>(labels, subgroups);
    gather_kernel<<<4096, 256>>>(features);
    sqn_kernel<<<1024, 256>>>();
    minmax_kernel<<<32, 256>>>();
    eps0_kernel<<<7, 256>>>();
    gemm_kernel<<<dim3(64, 72), 256>>>();
    transpose_kernel<<<dim3(16, 16, 56), dim3(32, 8)>>>();

    dim3 sgrid(64, NTASK);
    // init: writes buffer 0
    softmin_kernel<<<sgrid, 256>>>(0, 0, 1, 0);
    // 140 scan steps: step t reads t%2, writes 1-t%2
    for (int t = 0; t < 140; t++) {
        int bOld = t & 1;
        softmin_kernel<<<sgrid, 256>>>(t, 1, bOld, 1 - bOld);
    }
    // after t=139 (odd), result sits in buffer 0; final pass writes buffer 1
    softmin_kernel<<<sgrid, 256>>>(0, 2, 0, 1);
    reduce_kernel<<<1, 1024>>>(1, out);
}